// round 1
// baseline (speedup 1.0000x reference)
#include <cuda_runtime.h>
#include <math.h>
#include <stddef.h>

#define L_   2
#define D_   1024
#define H_   16
#define HD_  64
#define DFF_ 4096
#define V_   32000
#define B_   2
#define S_   1024
#define N_   (B_*S_)   // 2048 tokens

// ---------------- device scratch (static, no allocations) ----------------
__device__ float g_embm[(size_t)V_*D_];
__device__ float g_Wqkv[(size_t)L_*D_*3*D_];
__device__ float g_Wo  [(size_t)L_*D_*D_];
__device__ float g_W1  [(size_t)L_*D_*DFF_];
__device__ float g_W2  [(size_t)L_*DFF_*D_];
__device__ float g_g1  [L_*D_];
__device__ float g_g2  [L_*D_];
__device__ float g_gfm [D_];
__device__ float g_x   [(size_t)N_*D_];
__device__ float g_a   [(size_t)N_*D_];
__device__ float g_qkv [(size_t)N_*3*D_];
__device__ float g_att [(size_t)B_*H_*S_*S_];
__device__ float g_o   [(size_t)N_*D_];
__device__ float g_ff  [(size_t)N_*DFF_];
__device__ float g_logits[(size_t)N_*V_];
__device__ float g_nll [N_];

// ---------------- helpers ----------------
__device__ __forceinline__ float warp_sum(float v){
    #pragma unroll
    for (int o=16;o;o>>=1) v += __shfl_down_sync(0xffffffffu, v, o);
    return v;
}
__device__ __forceinline__ float warp_max(float v){
    #pragma unroll
    for (int o=16;o;o>>=1) v = fmaxf(v, __shfl_down_sync(0xffffffffu, v, o));
    return v;
}

// blockDim.x must be 256
template<bool MAXRED>
__device__ __forceinline__ float block_reduce(float v){
    __shared__ float sh[8];
    int tid = threadIdx.x;
    v = MAXRED ? warp_max(v) : warp_sum(v);
    __syncthreads();
    if ((tid & 31) == 0) sh[tid>>5] = v;
    __syncthreads();
    if (tid < 32){
        float a = (tid < 8) ? sh[tid] : (MAXRED ? -3.402823e38f : 0.f);
        a = MAXRED ? warp_max(a) : warp_sum(a);
        if (tid == 0) sh[0] = a;
    }
    __syncthreads();
    return sh[0];
}

__device__ __forceinline__ float gelu_f(float x){
    float x3 = x*x*x;
    return 0.5f*x*(1.f + tanhf(0.7978845608028654f*(x + 0.044715f*x3)));
}

// ---------------- merge: out = base + l0*delta0 + l1*delta1 ----------------
__global__ void merge_kernel(const float* __restrict__ base,
                             const float* __restrict__ delta,
                             const float* __restrict__ lam,
                             float* __restrict__ out, size_t n){
    size_t n4 = n >> 2;
    float l0 = lam[0], l1 = lam[1];
    const float4* b4 = (const float4*)base;
    const float4* d0 = (const float4*)delta;
    const float4* d1 = (const float4*)(delta + n);
    float4* o4 = (float4*)out;
    for (size_t i = (size_t)blockIdx.x*blockDim.x + threadIdx.x; i < n4;
         i += (size_t)gridDim.x*blockDim.x){
        float4 b = b4[i], x0 = d0[i], x1 = d1[i], r;
        r.x = b.x + l0*x0.x + l1*x1.x;
        r.y = b.y + l0*x0.y + l1*x1.y;
        r.z = b.z + l0*x0.z + l1*x1.z;
        r.w = b.w + l0*x0.w + l1*x1.w;
        o4[i] = r;
    }
}

// ---------------- gather: x[t] = embm[ids[t]] ----------------
__global__ void gather_kernel(const int* __restrict__ ids,
                              const float* __restrict__ embm,
                              float* __restrict__ x){
    int t = blockIdx.x;
    int id = ids[t];
    const float4* src = (const float4*)(embm + (size_t)id*D_);
    float4* dst = (float4*)(x + (size_t)t*D_);
    for (int d = threadIdx.x; d < D_/4; d += blockDim.x) dst[d] = src[d];
}

// ---------------- layernorm: out = (x-mu)*rsqrt(var+eps)*g ----------------
__global__ void ln_kernel(const float* __restrict__ x,
                          const float* __restrict__ g,
                          float* __restrict__ out){
    int t = blockIdx.x;
    int tid = threadIdx.x;
    const float* xr = x + (size_t)t*D_;
    float s = 0.f, ss = 0.f;
    for (int d = tid; d < D_; d += 256){ float v = xr[d]; s += v; ss = fmaf(v, v, ss); }
    float tots = block_reduce<false>(s);
    float totss = block_reduce<false>(ss);
    float mu = tots * (1.f/D_);
    float var = totss * (1.f/D_) - mu*mu;
    float inv = rsqrtf(var + 1e-5f);
    float* orow = out + (size_t)t*D_;
    for (int d = tid; d < D_; d += 256) orow[d] = (xr[d]-mu)*inv*g[d];
}

// ---------------- SGEMM NN: C = [Res +] A(MxK) @ B(KxN), optional GELU ----
template<int ACT, int RES>
__global__ void sgemm_nn(int M, int N, int K,
                         const float* __restrict__ A,
                         const float* __restrict__ B,
                         const float* __restrict__ Res,
                         float* __restrict__ C){
    __shared__ float As[16][68];
    __shared__ float Bs[16][68];
    int tx = threadIdx.x, ty = threadIdx.y;
    int tid = ty*16 + tx;
    int row0 = blockIdx.y*64, col0 = blockIdx.x*64;
    float acc[4][4] = {};
    for (int k0 = 0; k0 < K; k0 += 16){
        #pragma unroll
        for (int i = tid; i < 1024; i += 256){
            int mm = i >> 4, kk = i & 15;
            As[kk][mm] = A[(size_t)(row0+mm)*K + k0 + kk];
        }
        #pragma unroll
        for (int i = tid; i < 1024; i += 256){
            int kk = i >> 6, nn = i & 63;
            Bs[kk][nn] = B[(size_t)(k0+kk)*N + col0 + nn];
        }
        __syncthreads();
        #pragma unroll
        for (int kk = 0; kk < 16; kk++){
            float a[4], b[4];
            #pragma unroll
            for (int i2 = 0; i2 < 4; i2++) a[i2] = As[kk][ty*4+i2];
            #pragma unroll
            for (int j = 0; j < 4; j++) b[j] = Bs[kk][tx*4+j];
            #pragma unroll
            for (int i2 = 0; i2 < 4; i2++)
                #pragma unroll
                for (int j = 0; j < 4; j++)
                    acc[i2][j] = fmaf(a[i2], b[j], acc[i2][j]);
        }
        __syncthreads();
    }
    #pragma unroll
    for (int i2 = 0; i2 < 4; i2++){
        int r = row0 + ty*4 + i2;
        #pragma unroll
        for (int j = 0; j < 4; j++){
            int c = col0 + tx*4 + j;
            float v = acc[i2][j];
            if (RES) v += Res[(size_t)r*N + c];
            if (ACT) v = gelu_f(v);
            C[(size_t)r*N + c] = v;
        }
    }
}

// ---------------- SGEMM NT: C = A(MxK) @ B(NxK)^T ----------------
__global__ void sgemm_nt(int M, int N, int K,
                         const float* __restrict__ A,
                         const float* __restrict__ B,
                         float* __restrict__ C){
    __shared__ float As[16][68];
    __shared__ float Bs[16][68];
    int tx = threadIdx.x, ty = threadIdx.y;
    int tid = ty*16 + tx;
    int row0 = blockIdx.y*64, col0 = blockIdx.x*64;
    float acc[4][4] = {};
    for (int k0 = 0; k0 < K; k0 += 16){
        #pragma unroll
        for (int i = tid; i < 1024; i += 256){
            int mm = i >> 4, kk = i & 15;
            As[kk][mm] = A[(size_t)(row0+mm)*K + k0 + kk];
        }
        #pragma unroll
        for (int i = tid; i < 1024; i += 256){
            int nn = i >> 4, kk = i & 15;
            Bs[kk][nn] = B[(size_t)(col0+nn)*K + k0 + kk];
        }
        __syncthreads();
        #pragma unroll
        for (int kk = 0; kk < 16; kk++){
            float a[4], b[4];
            #pragma unroll
            for (int i2 = 0; i2 < 4; i2++) a[i2] = As[kk][ty*4+i2];
            #pragma unroll
            for (int j = 0; j < 4; j++) b[j] = Bs[kk][tx*4+j];
            #pragma unroll
            for (int i2 = 0; i2 < 4; i2++)
                #pragma unroll
                for (int j = 0; j < 4; j++)
                    acc[i2][j] = fmaf(a[i2], b[j], acc[i2][j]);
        }
        __syncthreads();
    }
    #pragma unroll
    for (int i2 = 0; i2 < 4; i2++){
        int r = row0 + ty*4 + i2;
        #pragma unroll
        for (int j = 0; j < 4; j++){
            int c = col0 + tx*4 + j;
            C[(size_t)r*N + c] = acc[i2][j];
        }
    }
}

// ---------------- attention scores: att[q,k] = q·k / 8 (k-tiles <= diag) ---
__global__ void attn_scores(const float* __restrict__ qkv, float* __restrict__ att){
    int k0 = blockIdx.x*64, q0 = blockIdx.y*64;
    if (k0 > q0) return;                // strictly-above-diagonal tiles never read
    int bh = blockIdx.z;
    int b = bh >> 4, h = bh & 15;
    __shared__ float Qs[64][65];
    __shared__ float Ks[64][65];
    int tid = threadIdx.y*16 + threadIdx.x;
    for (int i = tid; i < 4096; i += 256){
        int r = i >> 6, d = i & 63;
        Qs[r][d] = qkv[(size_t)(b*S_ + q0 + r)*(3*D_) + h*HD_ + d];
        Ks[r][d] = qkv[(size_t)(b*S_ + k0 + r)*(3*D_) + D_ + h*HD_ + d];
    }
    __syncthreads();
    float acc[4][4] = {};
    #pragma unroll
    for (int d = 0; d < 64; d++){
        float a[4], bb[4];
        #pragma unroll
        for (int i = 0; i < 4; i++) a[i] = Qs[threadIdx.y*4+i][d];
        #pragma unroll
        for (int j = 0; j < 4; j++) bb[j] = Ks[threadIdx.x*4+j][d];
        #pragma unroll
        for (int i = 0; i < 4; i++)
            #pragma unroll
            for (int j = 0; j < 4; j++)
                acc[i][j] = fmaf(a[i], bb[j], acc[i][j]);
    }
    size_t base = (size_t)bh * S_ * S_;
    #pragma unroll
    for (int i = 0; i < 4; i++){
        int q = q0 + threadIdx.y*4 + i;
        #pragma unroll
        for (int j = 0; j < 4; j++){
            int k = k0 + threadIdx.x*4 + j;
            att[base + (size_t)q*S_ + k] = acc[i][j]*0.125f;
        }
    }
}

// ---------------- causal softmax over k<=q; zeros for k>q ----------------
__global__ void softmax_kernel(float* __restrict__ att){
    int q = blockIdx.x;
    int bh = blockIdx.y;
    int tid = threadIdx.x;
    float* row = att + ((size_t)bh*S_ + q)*S_;
    int len = q + 1;
    float mx = -3.402823e38f;
    for (int k = tid; k < len; k += 256) mx = fmaxf(mx, row[k]);
    mx = block_reduce<true>(mx);
    float sum = 0.f;
    for (int k = tid; k < len; k += 256){
        float e = expf(row[k] - mx);
        row[k] = e;
        sum += e;
    }
    sum = block_reduce<false>(sum);
    float rinv = 1.f / sum;
    for (int k = tid; k < S_; k += 256)
        row[k] = (k < len) ? row[k]*rinv : 0.f;
}

// ---------------- o = att @ v ----------------
__global__ void attn_o(const float* __restrict__ att, const float* __restrict__ qkv,
                       float* __restrict__ o){
    int q0 = blockIdx.x*64;
    int bh = blockIdx.y;
    int b = bh >> 4, h = bh & 15;
    __shared__ float Ps[64][65];
    __shared__ float Vs[64][65];
    int tid = threadIdx.y*16 + threadIdx.x;
    float acc[4][4] = {};
    size_t abase = (size_t)bh*S_*S_;
    for (int k0 = 0; k0 <= q0; k0 += 64){
        for (int i = tid; i < 4096; i += 256){
            int r = i >> 6, c = i & 63;
            Ps[r][c] = att[abase + (size_t)(q0+r)*S_ + k0 + c];
            Vs[r][c] = qkv[(size_t)(b*S_ + k0 + r)*(3*D_) + 2*D_ + h*HD_ + c];
        }
        __syncthreads();
        #pragma unroll
        for (int kk = 0; kk < 64; kk++){
            float a[4], bb[4];
            #pragma unroll
            for (int i = 0; i < 4; i++) a[i] = Ps[threadIdx.y*4+i][kk];
            #pragma unroll
            for (int j = 0; j < 4; j++) bb[j] = Vs[kk][threadIdx.x*4+j];
            #pragma unroll
            for (int i = 0; i < 4; i++)
                #pragma unroll
                for (int j = 0; j < 4; j++)
                    acc[i][j] = fmaf(a[i], bb[j], acc[i][j]);
        }
        __syncthreads();
    }
    #pragma unroll
    for (int i = 0; i < 4; i++){
        int q = q0 + threadIdx.y*4 + i;
        #pragma unroll
        for (int j = 0; j < 4; j++){
            int d = threadIdx.x*4 + j;
            o[(size_t)(b*S_ + q)*D_ + h*HD_ + d] = acc[i][j];
        }
    }
}

// ---------------- per-token NLL: logsumexp - logit[target] ----------------
__global__ void nll_kernel(const int* __restrict__ labels,
                           const float* __restrict__ logits,
                           float* __restrict__ nll){
    int t = blockIdx.x;
    int tid = threadIdx.x;
    int b = t >> 10, s = t & (S_-1);
    if (s == S_-1){ if (tid == 0) nll[t] = 0.f; return; }
    const float* row = logits + (size_t)t*V_;
    float mx = -3.402823e38f;
    for (int i = tid; i < V_; i += 256) mx = fmaxf(mx, row[i]);
    mx = block_reduce<true>(mx);
    float sum = 0.f;
    for (int i = tid; i < V_; i += 256) sum += expf(row[i] - mx);
    sum = block_reduce<false>(sum);
    if (tid == 0){
        int tgt = labels[b*S_ + s + 1];
        nll[t] = logf(sum) + mx - row[tgt];
    }
}

// ---------------- final mean ----------------
__global__ void final_reduce(const float* __restrict__ nll, float* __restrict__ out){
    float s = 0.f;
    for (int t = threadIdx.x; t < N_; t += 256)
        if ((t & (S_-1)) != S_-1) s += nll[t];
    s = block_reduce<false>(s);
    if (threadIdx.x == 0) out[0] = s * (1.f/(B_*(S_-1)));
}

// ---------------- host launch ----------------
static inline int mgrid(size_t n){
    size_t n4 = n >> 2;
    size_t b = (n4 + 255) / 256;
    return (int)b;
}

extern "C" void kernel_launch(void* const* d_in, const int* in_sizes, int n_in,
                              void* d_out, int out_size){
    const int*   ids    = (const int*)  d_in[0];
    const int*   labels = (const int*)  d_in[1];
    const float* lam    = (const float*)d_in[2];
    const float* emb    = (const float*)d_in[3];
    const float* Wqkv   = (const float*)d_in[4];
    const float* Wo     = (const float*)d_in[5];
    const float* W1     = (const float*)d_in[6];
    const float* W2     = (const float*)d_in[7];
    const float* g1     = (const float*)d_in[8];
    const float* g2     = (const float*)d_in[9];
    const float* gf     = (const float*)d_in[10];
    const float* d_emb  = (const float*)d_in[11];
    const float* d_Wqkv = (const float*)d_in[12];
    const float* d_Wo   = (const float*)d_in[13];
    const float* d_W1   = (const float*)d_in[14];
    const float* d_W2   = (const float*)d_in[15];
    const float* d_g1   = (const float*)d_in[16];
    const float* d_g2   = (const float*)d_in[17];
    const float* d_gf   = (const float*)d_in[18];

    float *p_embm, *p_Wqkv, *p_Wo, *p_W1, *p_W2, *p_g1, *p_g2, *p_gf;
    float *p_x, *p_a, *p_qkv, *p_att, *p_o, *p_ff, *p_logits, *p_nll;
    cudaGetSymbolAddress((void**)&p_embm,   g_embm);
    cudaGetSymbolAddress((void**)&p_Wqkv,   g_Wqkv);
    cudaGetSymbolAddress((void**)&p_Wo,     g_Wo);
    cudaGetSymbolAddress((void**)&p_W1,     g_W1);
    cudaGetSymbolAddress((void**)&p_W2,     g_W2);
    cudaGetSymbolAddress((void**)&p_g1,     g_g1);
    cudaGetSymbolAddress((void**)&p_g2,     g_g2);
    cudaGetSymbolAddress((void**)&p_gf,     g_gfm);
    cudaGetSymbolAddress((void**)&p_x,      g_x);
    cudaGetSymbolAddress((void**)&p_a,      g_a);
    cudaGetSymbolAddress((void**)&p_qkv,    g_qkv);
    cudaGetSymbolAddress((void**)&p_att,    g_att);
    cudaGetSymbolAddress((void**)&p_o,      g_o);
    cudaGetSymbolAddress((void**)&p_ff,     g_ff);
    cudaGetSymbolAddress((void**)&p_logits, g_logits);
    cudaGetSymbolAddress((void**)&p_nll,    g_nll);

    // ---- merge weights ----
    size_t n;
    n = (size_t)V_*D_;        merge_kernel<<<mgrid(n),256>>>(emb,  d_emb,  lam, p_embm, n);
    n = (size_t)L_*D_*3*D_;   merge_kernel<<<mgrid(n),256>>>(Wqkv, d_Wqkv, lam, p_Wqkv, n);
    n = (size_t)L_*D_*D_;     merge_kernel<<<mgrid(n),256>>>(Wo,   d_Wo,   lam, p_Wo,   n);
    n = (size_t)L_*D_*DFF_;   merge_kernel<<<mgrid(n),256>>>(W1,   d_W1,   lam, p_W1,   n);
    n = (size_t)L_*DFF_*D_;   merge_kernel<<<mgrid(n),256>>>(W2,   d_W2,   lam, p_W2,   n);
    n = (size_t)L_*D_;        merge_kernel<<<mgrid(n),256>>>(g1,   d_g1,   lam, p_g1,   n);
    n = (size_t)L_*D_;        merge_kernel<<<mgrid(n),256>>>(g2,   d_g2,   lam, p_g2,   n);
    n = (size_t)D_;           merge_kernel<<<mgrid(n),256>>>(gf,   d_gf,   lam, p_gf,   n);

    // ---- embed ----
    gather_kernel<<<N_, 256>>>(ids, p_embm, p_x);

    dim3 thr(16,16);
    for (int l = 0; l < L_; l++){
        // attn
        ln_kernel<<<N_,256>>>(p_x, p_g1 + l*D_, p_a);
        sgemm_nn<0,0><<<dim3(3*D_/64, N_/64), thr>>>(N_, 3*D_, D_, p_a,
                         p_Wqkv + (size_t)l*D_*3*D_, nullptr, p_qkv);
        attn_scores<<<dim3(S_/64, S_/64, B_*H_), thr>>>(p_qkv, p_att);
        softmax_kernel<<<dim3(S_, B_*H_), 256>>>(p_att);
        attn_o<<<dim3(S_/64, B_*H_), thr>>>(p_att, p_qkv, p_o);
        sgemm_nn<0,1><<<dim3(D_/64, N_/64), thr>>>(N_, D_, D_, p_o,
                         p_Wo + (size_t)l*D_*D_, p_x, p_x);
        // ffn
        ln_kernel<<<N_,256>>>(p_x, p_g2 + l*D_, p_a);
        sgemm_nn<1,0><<<dim3(DFF_/64, N_/64), thr>>>(N_, DFF_, D_, p_a,
                         p_W1 + (size_t)l*D_*DFF_, nullptr, p_ff);
        sgemm_nn<0,1><<<dim3(D_/64, N_/64), thr>>>(N_, D_, DFF_, p_ff,
                         p_W2 + (size_t)l*DFF_*D_, p_x, p_x);
    }

    // ---- head ----
    ln_kernel<<<N_,256>>>(p_x, p_gf, p_a);
    sgemm_nt<<<dim3(V_/64, N_/64), thr>>>(N_, V_, D_, p_a, p_embm, p_logits);
    nll_kernel<<<N_,256>>>(labels, p_logits, p_nll);
    final_reduce<<<1,256>>>(p_nll, (float*)d_out);
}

// round 3
// speedup vs baseline: 3.3270x; 3.3270x over previous
#include <cuda_runtime.h>
#include <math.h>
#include <stddef.h>
#include <stdint.h>

#define L_   2
#define D_   1024
#define H_   16
#define HD_  64
#define DFF_ 4096
#define V_   32000
#define B_   2
#define S_   1024
#define N_   (B_*S_)   // 2048 tokens

// ---------------- device scratch (static, no allocations) ----------------
__device__ float g_embm[(size_t)V_*D_];
__device__ float g_Wqkv[(size_t)L_*D_*3*D_];
__device__ float g_Wo  [(size_t)L_*D_*D_];
__device__ float g_W1  [(size_t)L_*D_*DFF_];
__device__ float g_W2  [(size_t)L_*DFF_*D_];
__device__ float g_g1  [L_*D_];
__device__ float g_g2  [L_*D_];
__device__ float g_gfm [D_];
__device__ float g_x   [(size_t)N_*D_];
__device__ float g_a   [(size_t)N_*D_];
__device__ float g_qkv [(size_t)N_*3*D_];
__device__ float g_att [(size_t)B_*H_*S_*S_];
__device__ float g_o   [(size_t)N_*D_];
__device__ float g_ff  [(size_t)N_*DFF_];
__device__ float g_logits[(size_t)N_*V_];
__device__ float g_nll [N_];

// ---------------- helpers ----------------
__device__ __forceinline__ float warp_sum(float v){
    #pragma unroll
    for (int o=16;o;o>>=1) v += __shfl_down_sync(0xffffffffu, v, o);
    return v;
}
__device__ __forceinline__ float warp_max(float v){
    #pragma unroll
    for (int o=16;o;o>>=1) v = fmaxf(v, __shfl_down_sync(0xffffffffu, v, o));
    return v;
}

// blockDim.x must be 256
template<bool MAXRED>
__device__ __forceinline__ float block_reduce(float v){
    __shared__ float sh[8];
    int tid = threadIdx.x;
    v = MAXRED ? warp_max(v) : warp_sum(v);
    __syncthreads();
    if ((tid & 31) == 0) sh[tid>>5] = v;
    __syncthreads();
    if (tid < 32){
        float a = (tid < 8) ? sh[tid] : (MAXRED ? -3.402823e38f : 0.f);
        a = MAXRED ? warp_max(a) : warp_sum(a);
        if (tid == 0) sh[0] = a;
    }
    __syncthreads();
    return sh[0];
}

__device__ __forceinline__ float gelu_f(float x){
    float x3 = x*x*x;
    return 0.5f*x*(1.f + tanhf(0.7978845608028654f*(x + 0.044715f*x3)));
}

__device__ __forceinline__ unsigned f2tf32(float x){
    unsigned r; asm("cvt.rna.tf32.f32 %0, %1;" : "=r"(r) : "f"(x)); return r;
}
__device__ __forceinline__ float f2tf32f(float x){
    return __uint_as_float(f2tf32(x));
}

// ---------------- merge: out = base + l0*delta0 + l1*delta1 ----------------
__global__ void merge_kernel(const float* __restrict__ base,
                             const float* __restrict__ delta,
                             const float* __restrict__ lam,
                             float* __restrict__ out, size_t n){
    size_t n4 = n >> 2;
    float l0 = lam[0], l1 = lam[1];
    const float4* b4 = (const float4*)base;
    const float4* d0 = (const float4*)delta;
    const float4* d1 = (const float4*)(delta + n);
    float4* o4 = (float4*)out;
    for (size_t i = (size_t)blockIdx.x*blockDim.x + threadIdx.x; i < n4;
         i += (size_t)gridDim.x*blockDim.x){
        float4 b = b4[i], x0 = d0[i], x1 = d1[i], r;
        r.x = b.x + l0*x0.x + l1*x1.x;
        r.y = b.y + l0*x0.y + l1*x1.y;
        r.z = b.z + l0*x0.z + l1*x1.z;
        r.w = b.w + l0*x0.w + l1*x1.w;
        o4[i] = r;
    }
}

// ---------------- gather: x[t] = embm[ids[t]] ----------------
__global__ void gather_kernel(const int* __restrict__ ids,
                              const float* __restrict__ embm,
                              float* __restrict__ x){
    int t = blockIdx.x;
    int id = ids[t];
    const float4* src = (const float4*)(embm + (size_t)id*D_);
    float4* dst = (float4*)(x + (size_t)t*D_);
    for (int d = threadIdx.x; d < D_/4; d += blockDim.x) dst[d] = src[d];
}

// ---------------- layernorm ----------------
__global__ void ln_kernel(const float* __restrict__ x,
                          const float* __restrict__ g,
                          float* __restrict__ out){
    int t = blockIdx.x;
    int tid = threadIdx.x;
    const float* xr = x + (size_t)t*D_;
    float s = 0.f, ss = 0.f;
    for (int d = tid; d < D_; d += 256){ float v = xr[d]; s += v; ss = fmaf(v, v, ss); }
    float tots = block_reduce<false>(s);
    float totss = block_reduce<false>(ss);
    float mu = tots * (1.f/D_);
    float var = totss * (1.f/D_) - mu*mu;
    float inv = rsqrtf(var + 1e-5f);
    float* orow = out + (size_t)t*D_;
    for (int d = tid; d < D_; d += 256) orow[d] = (xr[d]-mu)*inv*g[d];
}

// ================= TF32 tensor-core GEMM =================
// C(MxN) = [Res +] [gelu] ( A(MxK) @ B )   B: KxN (TRANSB=0) or NxK row-major (TRANSB=1)
// Block: 256 thr, tile 128x128, BK=16. Warp tile 32x64 (4x2 warp grid).
// mma.sync.m16n8k8.tf32. Requires M%128==0, N%128==0, K%16==0.
#define AS_STRIDE 20
#define BS_STRIDE 136

template<int TRANSB, int ACT, int RES>
__global__ void __launch_bounds__(256) mma_gemm(int M, int N, int K,
                        const float* __restrict__ A,
                        const float* __restrict__ B,
                        const float* __restrict__ Res,
                        float* __restrict__ C){
    __shared__ float As[128*AS_STRIDE];
    __shared__ float Bs[128*AS_STRIDE > 16*BS_STRIDE ? 128*AS_STRIDE : 16*BS_STRIDE];

    const int tid  = threadIdx.x;
    const int lane = tid & 31;
    const int warp = tid >> 5;
    const int g    = lane >> 2;     // 0..7
    const int t    = lane & 3;      // 0..3
    const int wm   = warp >> 1;     // 0..3
    const int wn   = warp & 1;      // 0..1
    const int row0 = blockIdx.y * 128;
    const int col0 = blockIdx.x * 128;

    float c[2][8][4];
    #pragma unroll
    for (int i=0;i<2;i++)
        #pragma unroll
        for (int j=0;j<8;j++)
            #pragma unroll
            for (int k=0;k<4;k++) c[i][j][k]=0.f;

    // staging-load index precompute
    const int am0 = tid >> 2;            // 0..63
    const int ac  = (tid & 3) * 4;       // 0,4,8,12
    const int bkA = tid >> 5;            // 0..7 (NN)
    const int bn  = (tid & 31) * 4;      // 0..124 (NN)

    const float* Arow0 = A + (size_t)(row0 + am0)*K;
    const float* Arow1 = A + (size_t)(row0 + am0 + 64)*K;

    float4 ra0, ra1, rb0, rb1;
    // load tile 0
    {
        const int k0 = 0;
        ra0 = *(const float4*)(Arow0 + k0 + ac);
        ra1 = *(const float4*)(Arow1 + k0 + ac);
        if (TRANSB){
            rb0 = *(const float4*)(B + (size_t)(col0 + am0)*K + k0 + ac);
            rb1 = *(const float4*)(B + (size_t)(col0 + am0 + 64)*K + k0 + ac);
        } else {
            rb0 = *(const float4*)(B + (size_t)(k0 + bkA)*N + col0 + bn);
            rb1 = *(const float4*)(B + (size_t)(k0 + bkA + 8)*N + col0 + bn);
        }
    }

    const int KT = K >> 4;
    for (int kt = 0; kt < KT; kt++){
        // ---- store staged tile to smem (converted to tf32) ----
        {
            float4 v;
            v.x=f2tf32f(ra0.x); v.y=f2tf32f(ra0.y); v.z=f2tf32f(ra0.z); v.w=f2tf32f(ra0.w);
            *(float4*)&As[am0*AS_STRIDE + ac] = v;
            v.x=f2tf32f(ra1.x); v.y=f2tf32f(ra1.y); v.z=f2tf32f(ra1.z); v.w=f2tf32f(ra1.w);
            *(float4*)&As[(am0+64)*AS_STRIDE + ac] = v;
            if (TRANSB){
                v.x=f2tf32f(rb0.x); v.y=f2tf32f(rb0.y); v.z=f2tf32f(rb0.z); v.w=f2tf32f(rb0.w);
                *(float4*)&Bs[am0*AS_STRIDE + ac] = v;
                v.x=f2tf32f(rb1.x); v.y=f2tf32f(rb1.y); v.z=f2tf32f(rb1.z); v.w=f2tf32f(rb1.w);
                *(float4*)&Bs[(am0+64)*AS_STRIDE + ac] = v;
            } else {
                v.x=f2tf32f(rb0.x); v.y=f2tf32f(rb0.y); v.z=f2tf32f(rb0.z); v.w=f2tf32f(rb0.w);
                *(float4*)&Bs[bkA*BS_STRIDE + bn] = v;
                v.x=f2tf32f(rb1.x); v.y=f2tf32f(rb1.y); v.z=f2tf32f(rb1.z); v.w=f2tf32f(rb1.w);
                *(float4*)&Bs[(bkA+8)*BS_STRIDE + bn] = v;
            }
        }
        __syncthreads();

        // ---- prefetch next tile ----
        if (kt + 1 < KT){
            const int k0 = (kt + 1) << 4;
            ra0 = *(const float4*)(Arow0 + k0 + ac);
            ra1 = *(const float4*)(Arow1 + k0 + ac);
            if (TRANSB){
                rb0 = *(const float4*)(B + (size_t)(col0 + am0)*K + k0 + ac);
                rb1 = *(const float4*)(B + (size_t)(col0 + am0 + 64)*K + k0 + ac);
            } else {
                rb0 = *(const float4*)(B + (size_t)(k0 + bkA)*N + col0 + bn);
                rb1 = *(const float4*)(B + (size_t)(k0 + bkA + 8)*N + col0 + bn);
            }
        }

        // ---- compute 2 k8 sub-steps ----
        #pragma unroll
        for (int ks = 0; ks < 16; ks += 8){
            unsigned af[2][4];
            unsigned bf[8][2];
            #pragma unroll
            for (int mt = 0; mt < 2; mt++){
                int base = (wm*32 + mt*16 + g)*AS_STRIDE + ks + t;
                af[mt][0] = __float_as_uint(As[base]);
                af[mt][1] = __float_as_uint(As[base + 8*AS_STRIDE]);
                af[mt][2] = __float_as_uint(As[base + 4]);
                af[mt][3] = __float_as_uint(As[base + 8*AS_STRIDE + 4]);
            }
            #pragma unroll
            for (int nt = 0; nt < 8; nt++){
                if (TRANSB){
                    int base = (wn*64 + nt*8 + g)*AS_STRIDE + ks + t;
                    bf[nt][0] = __float_as_uint(Bs[base]);
                    bf[nt][1] = __float_as_uint(Bs[base + 4]);
                } else {
                    int col = wn*64 + nt*8 + g;
                    bf[nt][0] = __float_as_uint(Bs[(ks + t)*BS_STRIDE + col]);
                    bf[nt][1] = __float_as_uint(Bs[(ks + t + 4)*BS_STRIDE + col]);
                }
            }
            #pragma unroll
            for (int mt = 0; mt < 2; mt++)
                #pragma unroll
                for (int nt = 0; nt < 8; nt++){
                    asm volatile(
                        "mma.sync.aligned.m16n8k8.row.col.f32.tf32.tf32.f32 "
                        "{%0,%1,%2,%3}, {%4,%5,%6,%7}, {%8,%9}, {%0,%1,%2,%3};\n"
                        : "+f"(c[mt][nt][0]), "+f"(c[mt][nt][1]),
                          "+f"(c[mt][nt][2]), "+f"(c[mt][nt][3])
                        : "r"(af[mt][0]), "r"(af[mt][1]), "r"(af[mt][2]), "r"(af[mt][3]),
                          "r"(bf[nt][0]), "r"(bf[nt][1]));
                }
        }
        __syncthreads();
    }

    // ---- epilogue ----
    #pragma unroll
    for (int mt = 0; mt < 2; mt++){
        int r0 = row0 + wm*32 + mt*16 + g;
        #pragma unroll
        for (int nt = 0; nt < 8; nt++){
            int cc = col0 + wn*64 + nt*8 + 2*t;
            float v0 = c[mt][nt][0], v1 = c[mt][nt][1];
            float v2 = c[mt][nt][2], v3 = c[mt][nt][3];
            if (RES){
                v0 += Res[(size_t)r0*N + cc];
                v1 += Res[(size_t)r0*N + cc + 1];
                v2 += Res[(size_t)(r0+8)*N + cc];
                v3 += Res[(size_t)(r0+8)*N + cc + 1];
            }
            if (ACT){
                v0 = gelu_f(v0); v1 = gelu_f(v1);
                v2 = gelu_f(v2); v3 = gelu_f(v3);
            }
            C[(size_t)r0*N + cc]       = v0;
            C[(size_t)r0*N + cc + 1]   = v1;
            C[(size_t)(r0+8)*N + cc]     = v2;
            C[(size_t)(r0+8)*N + cc + 1] = v3;
        }
    }
}

// ---------------- attention scores: att[q,k] = q·k / 8 ----------------
__global__ void attn_scores(const float* __restrict__ qkv, float* __restrict__ att){
    int k0 = blockIdx.x*64, q0 = blockIdx.y*64;
    if (k0 > q0) return;
    int bh = blockIdx.z;
    int b = bh >> 4, h = bh & 15;
    __shared__ float Qs[64][65];
    __shared__ float Ks[64][65];
    int tid = threadIdx.y*16 + threadIdx.x;
    for (int i = tid; i < 4096; i += 256){
        int r = i >> 6, d = i & 63;
        Qs[r][d] = qkv[(size_t)(b*S_ + q0 + r)*(3*D_) + h*HD_ + d];
        Ks[r][d] = qkv[(size_t)(b*S_ + k0 + r)*(3*D_) + D_ + h*HD_ + d];
    }
    __syncthreads();
    float acc[4][4] = {};
    #pragma unroll
    for (int d = 0; d < 64; d++){
        float a[4], bb[4];
        #pragma unroll
        for (int i = 0; i < 4; i++) a[i] = Qs[threadIdx.y*4+i][d];
        #pragma unroll
        for (int j = 0; j < 4; j++) bb[j] = Ks[threadIdx.x*4+j][d];
        #pragma unroll
        for (int i = 0; i < 4; i++)
            #pragma unroll
            for (int j = 0; j < 4; j++)
                acc[i][j] = fmaf(a[i], bb[j], acc[i][j]);
    }
    size_t base = (size_t)bh * S_ * S_;
    #pragma unroll
    for (int i = 0; i < 4; i++){
        int q = q0 + threadIdx.y*4 + i;
        #pragma unroll
        for (int j = 0; j < 4; j++){
            int k = k0 + threadIdx.x*4 + j;
            att[base + (size_t)q*S_ + k] = acc[i][j]*0.125f;
        }
    }
}

// ---------------- causal softmax ----------------
__global__ void softmax_kernel(float* __restrict__ att){
    int q = blockIdx.x;
    int bh = blockIdx.y;
    int tid = threadIdx.x;
    float* row = att + ((size_t)bh*S_ + q)*S_;
    int len = q + 1;
    float mx = -3.402823e38f;
    for (int k = tid; k < len; k += 256) mx = fmaxf(mx, row[k]);
    mx = block_reduce<true>(mx);
    float sum = 0.f;
    for (int k = tid; k < len; k += 256){
        float e = expf(row[k] - mx);
        row[k] = e;
        sum += e;
    }
    sum = block_reduce<false>(sum);
    float rinv = 1.f / sum;
    for (int k = tid; k < S_; k += 256)
        row[k] = (k < len) ? row[k]*rinv : 0.f;
}

// ---------------- o = att @ v ----------------
__global__ void attn_o(const float* __restrict__ att, const float* __restrict__ qkv,
                       float* __restrict__ o){
    int q0 = blockIdx.x*64;
    int bh = blockIdx.y;
    int b = bh >> 4, h = bh & 15;
    __shared__ float Ps[64][65];
    __shared__ float Vs[64][65];
    int tid = threadIdx.y*16 + threadIdx.x;
    float acc[4][4] = {};
    size_t abase = (size_t)bh*S_*S_;
    for (int k0 = 0; k0 <= q0; k0 += 64){
        for (int i = tid; i < 4096; i += 256){
            int r = i >> 6, c = i & 63;
            Ps[r][c] = att[abase + (size_t)(q0+r)*S_ + k0 + c];
            Vs[r][c] = qkv[(size_t)(b*S_ + k0 + r)*(3*D_) + 2*D_ + h*HD_ + c];
        }
        __syncthreads();
        #pragma unroll
        for (int kk = 0; kk < 64; kk++){
            float a[4], bb[4];
            #pragma unroll
            for (int i = 0; i < 4; i++) a[i] = Ps[threadIdx.y*4+i][kk];
            #pragma unroll
            for (int j = 0; j < 4; j++) bb[j] = Vs[kk][threadIdx.x*4+j];
            #pragma unroll
            for (int i = 0; i < 4; i++)
                #pragma unroll
                for (int j = 0; j < 4; j++)
                    acc[i][j] = fmaf(a[i], bb[j], acc[i][j]);
        }
        __syncthreads();
    }
    #pragma unroll
    for (int i = 0; i < 4; i++){
        int q = q0 + threadIdx.y*4 + i;
        #pragma unroll
        for (int j = 0; j < 4; j++){
            int d = threadIdx.x*4 + j;
            o[(size_t)(b*S_ + q)*D_ + h*HD_ + d] = acc[i][j];
        }
    }
}

// ---------------- per-token NLL ----------------
__global__ void nll_kernel(const int* __restrict__ labels,
                           const float* __restrict__ logits,
                           float* __restrict__ nll){
    int t = blockIdx.x;
    int tid = threadIdx.x;
    int b = t >> 10, s = t & (S_-1);
    if (s == S_-1){ if (tid == 0) nll[t] = 0.f; return; }
    const float* row = logits + (size_t)t*V_;
    float mx = -3.402823e38f;
    for (int i = tid; i < V_; i += 256) mx = fmaxf(mx, row[i]);
    mx = block_reduce<true>(mx);
    float sum = 0.f;
    for (int i = tid; i < V_; i += 256) sum += expf(row[i] - mx);
    sum = block_reduce<false>(sum);
    if (tid == 0){
        int tgt = labels[b*S_ + s + 1];
        nll[t] = logf(sum) + mx - row[tgt];
    }
}

// ---------------- final mean ----------------
__global__ void final_reduce(const float* __restrict__ nll, float* __restrict__ out){
    float s = 0.f;
    for (int t = threadIdx.x; t < N_; t += 256)
        if ((t & (S_-1)) != S_-1) s += nll[t];
    s = block_reduce<false>(s);
    if (threadIdx.x == 0) out[0] = s * (1.f/(B_*(S_-1)));
}

// ---------------- host launch ----------------
static inline int mgrid(size_t n){
    size_t n4 = n >> 2;
    size_t b = (n4 + 255) / 256;
    return (int)b;
}

extern "C" void kernel_launch(void* const* d_in, const int* in_sizes, int n_in,
                              void* d_out, int out_size){
    const int*   ids    = (const int*)  d_in[0];
    const int*   labels = (const int*)  d_in[1];
    const float* lam    = (const float*)d_in[2];
    const float* emb    = (const float*)d_in[3];
    const float* Wqkv   = (const float*)d_in[4];
    const float* Wo     = (const float*)d_in[5];
    const float* W1     = (const float*)d_in[6];
    const float* W2     = (const float*)d_in[7];
    const float* g1     = (const float*)d_in[8];
    const float* g2     = (const float*)d_in[9];
    const float* gf     = (const float*)d_in[10];
    const float* d_emb  = (const float*)d_in[11];
    const float* d_Wqkv = (const float*)d_in[12];
    const float* d_Wo   = (const float*)d_in[13];
    const float* d_W1   = (const float*)d_in[14];
    const float* d_W2   = (const float*)d_in[15];
    const float* d_g1   = (const float*)d_in[16];
    const float* d_g2   = (const float*)d_in[17];
    const float* d_gf   = (const float*)d_in[18];

    float *p_embm, *p_Wqkv, *p_Wo, *p_W1, *p_W2, *p_g1, *p_g2, *p_gf;
    float *p_x, *p_a, *p_qkv, *p_att, *p_o, *p_ff, *p_logits, *p_nll;
    cudaGetSymbolAddress((void**)&p_embm,   g_embm);
    cudaGetSymbolAddress((void**)&p_Wqkv,   g_Wqkv);
    cudaGetSymbolAddress((void**)&p_Wo,     g_Wo);
    cudaGetSymbolAddress((void**)&p_W1,     g_W1);
    cudaGetSymbolAddress((void**)&p_W2,     g_W2);
    cudaGetSymbolAddress((void**)&p_g1,     g_g1);
    cudaGetSymbolAddress((void**)&p_g2,     g_g2);
    cudaGetSymbolAddress((void**)&p_gf,     g_gfm);
    cudaGetSymbolAddress((void**)&p_x,      g_x);
    cudaGetSymbolAddress((void**)&p_a,      g_a);
    cudaGetSymbolAddress((void**)&p_qkv,    g_qkv);
    cudaGetSymbolAddress((void**)&p_att,    g_att);
    cudaGetSymbolAddress((void**)&p_o,      g_o);
    cudaGetSymbolAddress((void**)&p_ff,     g_ff);
    cudaGetSymbolAddress((void**)&p_logits, g_logits);
    cudaGetSymbolAddress((void**)&p_nll,    g_nll);

    // ---- merge weights ----
    size_t n;
    n = (size_t)V_*D_;        merge_kernel<<<mgrid(n),256>>>(emb,  d_emb,  lam, p_embm, n);
    n = (size_t)L_*D_*3*D_;   merge_kernel<<<mgrid(n),256>>>(Wqkv, d_Wqkv, lam, p_Wqkv, n);
    n = (size_t)L_*D_*D_;     merge_kernel<<<mgrid(n),256>>>(Wo,   d_Wo,   lam, p_Wo,   n);
    n = (size_t)L_*D_*DFF_;   merge_kernel<<<mgrid(n),256>>>(W1,   d_W1,   lam, p_W1,   n);
    n = (size_t)L_*DFF_*D_;   merge_kernel<<<mgrid(n),256>>>(W2,   d_W2,   lam, p_W2,   n);
    n = (size_t)L_*D_;        merge_kernel<<<mgrid(n),256>>>(g1,   d_g1,   lam, p_g1,   n);
    n = (size_t)L_*D_;        merge_kernel<<<mgrid(n),256>>>(g2,   d_g2,   lam, p_g2,   n);
    n = (size_t)D_;           merge_kernel<<<mgrid(n),256>>>(gf,   d_gf,   lam, p_gf,   n);

    // ---- embed ----
    gather_kernel<<<N_, 256>>>(ids, p_embm, p_x);

    dim3 thr(16,16);
    for (int l = 0; l < L_; l++){
        // attn
        ln_kernel<<<N_,256>>>(p_x, p_g1 + l*D_, p_a);
        mma_gemm<0,0,0><<<dim3(3*D_/128, N_/128), 256>>>(N_, 3*D_, D_, p_a,
                         p_Wqkv + (size_t)l*D_*3*D_, nullptr, p_qkv);
        attn_scores<<<dim3(S_/64, S_/64, B_*H_), thr>>>(p_qkv, p_att);
        softmax_kernel<<<dim3(S_, B_*H_), 256>>>(p_att);
        attn_o<<<dim3(S_/64, B_*H_), thr>>>(p_att, p_qkv, p_o);
        mma_gemm<0,0,1><<<dim3(D_/128, N_/128), 256>>>(N_, D_, D_, p_o,
                         p_Wo + (size_t)l*D_*D_, p_x, p_x);
        // ffn
        ln_kernel<<<N_,256>>>(p_x, p_g2 + l*D_, p_a);
        mma_gemm<0,1,0><<<dim3(DFF_/128, N_/128), 256>>>(N_, DFF_, D_, p_a,
                         p_W1 + (size_t)l*D_*DFF_, nullptr, p_ff);
        mma_gemm<0,0,1><<<dim3(D_/128, N_/128), 256>>>(N_, D_, DFF_, p_ff,
                         p_W2 + (size_t)l*DFF_*D_, p_x, p_x);
    }

    // ---- head ----
    ln_kernel<<<N_,256>>>(p_x, p_gf, p_a);
    mma_gemm<1,0,0><<<dim3(V_/128, N_/128), 256>>>(N_, V_, D_, p_a, p_embm,
                     nullptr, p_logits);
    nll_kernel<<<N_,256>>>(labels, p_logits, p_nll);
    final_reduce<<<1,256>>>(p_nll, (float*)d_out);
}